// round 15
// baseline (speedup 1.0000x reference)
#include <cuda_runtime.h>
#include <cuda_fp16.h>
#include <math.h>

#define N_NODES   100000
#define N_EDGES   1600000
#define E_TOT     (N_EDGES + N_NODES)
#define IN_CH     128
#define HID       64
#define OUT_CH    16
#define N_GRAPHS  512
#define NEG_SLOPE 0.2f

#define SCAN_BLK  512
#define N_SCAN_BLKS ((N_NODES + SCAN_BLK - 1) / SCAN_BLK)   // 196

// ---------------- scratch (device globals; no allocation allowed) ----------------
__device__ __half2 g_xl[(size_t)N_NODES * 32];
__device__ __half2 g_xr[(size_t)N_NODES * 32];
__device__ float   g_h[(size_t)N_NODES * HID];
__device__ float   g_pool[N_GRAPHS * HID];
__device__ float   g_cnt[N_GRAPHS];
__device__ float   g_y[N_GRAPHS * HID];
__device__ float   g_bnstat[2 * HID];   // [0:64) sum, [64:128) sum of squares
__device__ int     g_is64;

// CSR scratch
__device__ int g_deg[N_NODES];
__device__ int g_rowptr[N_NODES + 1];
__device__ int g_cursor[N_NODES];
__device__ int g_col[E_TOT];
__device__ int g_bsum[N_SCAN_BLKS];

// ---------------- aux streams/events ----------------
namespace {
struct Aux {
    cudaStream_t s2 = nullptr;
    cudaEvent_t  evFork = nullptr, evB = nullptr;
    Aux() {
        if (cudaStreamCreateWithFlags(&s2, cudaStreamNonBlocking) != cudaSuccess) {
            s2 = nullptr; return;
        }
        if (cudaEventCreateWithFlags(&evFork, cudaEventDisableTiming) != cudaSuccess) {
            evFork = nullptr; return;
        }
        if (cudaEventCreateWithFlags(&evB, cudaEventDisableTiming) != cudaSuccess) {
            evB = nullptr; return;
        }
    }
};
Aux g_aux;
}

// ---------------- packed helpers ----------------
__device__ __forceinline__ unsigned long long pack2(float lo, float hi) {
    unsigned long long r;
    asm("mov.b64 %0, {%1, %2};" : "=l"(r) : "f"(lo), "f"(hi));
    return r;
}
__device__ __forceinline__ void unpack2(unsigned long long v, float& lo, float& hi) {
    asm("mov.b64 {%0, %1}, %2;" : "=f"(lo), "=f"(hi) : "l"(v));
}
__device__ __forceinline__ void fma2(unsigned long long& d,
                                     unsigned long long a, unsigned long long b) {
    asm("fma.rn.f32x2 %0, %1, %2, %0;" : "+l"(d) : "l"(a), "l"(b));
}
__device__ __forceinline__ unsigned h2u(__half2 h) { return *(unsigned*)&h; }
__device__ __forceinline__ __half2 u2h(unsigned u) { return *(__half2*)&u; }

// ---------------- dtype detection ----------------
__global__ void detect_kernel(const int* __restrict__ w) {
    int ok64 = 1;
    for (int i = 0; i < 32; i++)
        if (w[2 * i + 1] != 0) ok64 = 0;
    g_is64 = ok64;
}

__device__ __forceinline__ int load_idx(const void* p, long long i) {
    if (g_is64) return (int)((const long long*)p)[i];
    return ((const int*)p)[i];
}

// ---------------- CSR build ----------------
__global__ void hist_kernel(const void* __restrict__ ei, int* __restrict__ deg) {
    int t = blockIdx.x * blockDim.x + threadIdx.x;
#pragma unroll
    for (int u = 0; u < 2; u++) {
        int e = t * 2 + u;
        if (e >= E_TOT) return;
        int dst = (e < N_EDGES) ? load_idx(ei, (long long)N_EDGES + e) : e - N_EDGES;
        atomicAdd(&deg[dst], 1);
    }
}

__global__ void scan1_kernel(const int* __restrict__ deg, int* __restrict__ rowptr,
                             int* __restrict__ bsum) {
    __shared__ int sh[SCAN_BLK];
    int i = blockIdx.x * SCAN_BLK + threadIdx.x;
    int v = (i < N_NODES) ? deg[i] : 0;
    sh[threadIdx.x] = v;
    __syncthreads();
    for (int o = 1; o < SCAN_BLK; o <<= 1) {
        int t = (threadIdx.x >= o) ? sh[threadIdx.x - o] : 0;
        __syncthreads();
        sh[threadIdx.x] += t;
        __syncthreads();
    }
    if (i < N_NODES) rowptr[i] = sh[threadIdx.x] - v;
    if (threadIdx.x == SCAN_BLK - 1) bsum[blockIdx.x] = sh[SCAN_BLK - 1];
}

__global__ void scan2_kernel(int* __restrict__ bsum) {
    int lane = threadIdx.x & 31;
    int acc = 0;
    for (int base = 0; base < N_SCAN_BLKS; base += 32) {
        int i = base + lane;
        int orig = (i < N_SCAN_BLKS) ? bsum[i] : 0;
        int v = orig;
#pragma unroll
        for (int o = 1; o < 32; o <<= 1) {
            int t = __shfl_up_sync(0xffffffffu, v, o);
            if (lane >= o) v += t;
        }
        if (i < N_SCAN_BLKS) bsum[i] = acc + v - orig;
        acc += __shfl_sync(0xffffffffu, v, 31);
    }
}

__global__ void scan3_kernel(int* __restrict__ rowptr, const int* __restrict__ bsum,
                             int* __restrict__ cursor) {
    int i = blockIdx.x * SCAN_BLK + threadIdx.x;
    if (i < N_NODES) {
        int v = rowptr[i] + bsum[blockIdx.x];
        rowptr[i] = v;
        cursor[i] = v;
    }
    if (i == 0) rowptr[N_NODES] = E_TOT;
}

__global__ void scatter_kernel(const void* __restrict__ ei,
                               int* __restrict__ cursor, int* __restrict__ col) {
    int t = blockIdx.x * blockDim.x + threadIdx.x;
#pragma unroll
    for (int u = 0; u < 2; u++) {
        int e = t * 2 + u;
        if (e >= E_TOT) return;
        int src, dst;
        if (e < N_EDGES) {
            src = load_idx(ei, e);
            dst = load_idx(ei, (long long)N_EDGES + e);
        } else {
            src = dst = e - N_EDGES;
        }
        int pos = atomicAdd(&cursor[dst], 1);
        col[pos] = src;
    }
}

// ---------------- dual linear: 64 nodes/block, 8 nodes x 2 ch/thread ---------
template <int IN>
__global__ __launch_bounds__(256) void dual_linear_kernel(
        const float* __restrict__ X,
        const float* __restrict__ Wl, const float* __restrict__ bl,
        const float* __restrict__ Wr, const float* __restrict__ br,
        __half2* __restrict__ XL, __half2* __restrict__ XR) {
    int node0 = blockIdx.x * 64;
    int c2    = threadIdx.x & 31;
    int sub   = threadIdx.x >> 5;
    __shared__ float xs[64][IN];

    for (int i = threadIdx.x; i < 64 * (IN / 4); i += 256) {
        int row = i / (IN / 4), colx = i % (IN / 4);
        int gr = node0 + row;
        if (gr >= N_NODES) gr = N_NODES - 1;
        ((float4*)xs[row])[colx] = ((const float4*)(X + (size_t)gr * IN))[colx];
    }
    __syncthreads();

    unsigned long long accl[8], accr[8];
    unsigned long long blv = *(const unsigned long long*)&bl[2 * c2];
    unsigned long long brv = *(const unsigned long long*)&br[2 * c2];
#pragma unroll
    for (int n = 0; n < 8; n++) { accl[n] = blv; accr[n] = brv; }

    const float (*xp)[IN] = (const float (*)[IN])xs[sub * 8];

    for (int k0 = 0; k0 < IN; k0 += 4) {
        float4 xv[8];
#pragma unroll
        for (int n = 0; n < 8; n++)
            xv[n] = *(const float4*)&xp[n][k0];
#pragma unroll
        for (int kk = 0; kk < 4; kk++) {
            unsigned long long wl2 =
                *(const unsigned long long*)&Wl[(k0 + kk) * HID + 2 * c2];
            unsigned long long wr2 =
                *(const unsigned long long*)&Wr[(k0 + kk) * HID + 2 * c2];
#pragma unroll
            for (int n = 0; n < 8; n++) {
                float xvv = (kk == 0) ? xv[n].x : (kk == 1) ? xv[n].y
                          : (kk == 2) ? xv[n].z : xv[n].w;
                unsigned long long xb = pack2(xvv, xvv);
                fma2(accl[n], xb, wl2);
                fma2(accr[n], xb, wr2);
            }
        }
    }

#pragma unroll
    for (int n = 0; n < 8; n++) {
        int node = node0 + sub * 8 + n;
        if (node < N_NODES) {
            float l0, l1, r0, r1;
            unpack2(accl[n], l0, l1);
            unpack2(accr[n], r0, r1);
            XL[(size_t)node * 32 + c2] = __floats2half2_rn(l0, l1);
            XR[(size_t)node * 32 + c2] = __floats2half2_rn(r0, r1);
        }
    }
}

// ---------------- GAT aggregate: 4 nodes/warp, 8 lanes/node, half2 math,
// half2 accumulators ----------------------------------------------------------
template <int POOL_MODE>
__global__ __launch_bounds__(256) void gat_agg_kernel(
        const int* __restrict__ rowptr, const int* __restrict__ col,
        const __half2* __restrict__ XL, const __half2* __restrict__ XR,
        const float* __restrict__ att, const float* __restrict__ bias,
        float* __restrict__ OUT, int do_relu,
        const void* __restrict__ batch, float* __restrict__ POOL,
        float* __restrict__ CNT) {
    int warp = threadIdx.x >> 5;
    int lane = threadIdx.x & 31;
    int q    = lane >> 3;      // 0..3: node slot within warp
    int hl   = lane & 7;       // channels 8*hl .. 8*hl+7
    int node = blockIdx.x * 32 + warp * 4 + q;   // grid sized exactly

    uint4 rraw = ((const uint4*)(XR + (size_t)node * 32))[hl];
    __half2 r0 = u2h(rraw.x), r1 = u2h(rraw.y), r2 = u2h(rraw.z), r3 = u2h(rraw.w);

    float4 aLo = ((const float4*)att)[2 * hl];
    float4 aHi = ((const float4*)att)[2 * hl + 1];
    __half2 at0 = __floats2half2_rn(aLo.x, aLo.y);
    __half2 at1 = __floats2half2_rn(aLo.z, aLo.w);
    __half2 at2 = __floats2half2_rn(aHi.x, aHi.y);
    __half2 at3 = __floats2half2_rn(aHi.z, aHi.w);
    const __half2 slope2 = __float2half2_rn(NEG_SLOPE);
    const __half2 zero2  = __float2half2_rn(0.0f);

    int beg = rowptr[node], end = rowptr[node + 1];
    int deg = end - beg;
    int m = deg;
    m = max(m, __shfl_xor_sync(0xffffffffu, m, 8));
    m = max(m, __shfl_xor_sync(0xffffffffu, m, 16));
    int maxit = m;

    __half2 ah0 = zero2, ah1 = zero2, ah2 = zero2, ah3 = zero2;
    float z = 0.0f;

    int e = beg;
    for (int it = 0; it < maxit; it += 2, e += 2) {
        bool v[2] = { e < end, e + 1 < end };
        int s[2];
        s[0] = v[0] ? __ldg(&col[e])     : node;
        s[1] = v[1] ? __ldg(&col[e + 1]) : node;

        uint4 lraw[2];
        lraw[0] = ((const uint4*)(XL + (size_t)s[0] * 32))[hl];
        lraw[1] = ((const uint4*)(XL + (size_t)s[1] * 32))[hl];

        __half2 p2[2];
#pragma unroll
        for (int u = 0; u < 2; u++) {
            __half2 h0 = __hadd2(u2h(lraw[u].x), r0);
            __half2 h1 = __hadd2(u2h(lraw[u].y), r1);
            __half2 h2 = __hadd2(u2h(lraw[u].z), r2);
            __half2 h3 = __hadd2(u2h(lraw[u].w), r3);
            h0 = __hmax2(h0, __hmul2(h0, slope2));
            h1 = __hmax2(h1, __hmul2(h1, slope2));
            h2 = __hmax2(h2, __hmul2(h2, slope2));
            h3 = __hmax2(h3, __hmul2(h3, slope2));
            __half2 t = __hfma2(h0, at0, __hmul2(h1, at1));
            t = __hfma2(h2, at2, t);
            p2[u] = __hfma2(h3, at3, t);
        }
#pragma unroll
        for (int o = 4; o; o >>= 1) {
#pragma unroll
            for (int u = 0; u < 2; u++)
                p2[u] = __hadd2(p2[u], u2h(__shfl_xor_sync(0xffffffffu, h2u(p2[u]), o)));
        }
#pragma unroll
        for (int u = 0; u < 2; u++) {
            float2 pf = __half22float2(p2[u]);
            float w = v[u] ? __expf(pf.x + pf.y) : 0.0f;
            z += w;
            __half2 w2 = __float2half2_rn(w);
            ah0 = __hfma2(w2, u2h(lraw[u].x), ah0);
            ah1 = __hfma2(w2, u2h(lraw[u].y), ah1);
            ah2 = __hfma2(w2, u2h(lraw[u].z), ah2);
            ah3 = __hfma2(w2, u2h(lraw[u].w), ah3);
        }
    }

    float inv = 1.0f / z;   // self-loop guarantees z > 0
    float2 f0 = __half22float2(ah0);
    float2 f1 = __half22float2(ah1);
    float2 f2 = __half22float2(ah2);
    float2 f3 = __half22float2(ah3);
    float4 bv0 = ((const float4*)bias)[2 * hl];
    float4 bv1 = ((const float4*)bias)[2 * hl + 1];
    float o0 = f0.x * inv + bv0.x;
    float o1 = f0.y * inv + bv0.y;
    float o2 = f1.x * inv + bv0.z;
    float o3 = f1.y * inv + bv0.w;
    float o4 = f2.x * inv + bv1.x;
    float o5 = f2.y * inv + bv1.y;
    float o6 = f3.x * inv + bv1.z;
    float o7 = f3.y * inv + bv1.w;

    if (POOL_MODE == 0) {
        if (do_relu) {
            o0 = fmaxf(o0, 0.0f); o1 = fmaxf(o1, 0.0f);
            o2 = fmaxf(o2, 0.0f); o3 = fmaxf(o3, 0.0f);
            o4 = fmaxf(o4, 0.0f); o5 = fmaxf(o5, 0.0f);
            o6 = fmaxf(o6, 0.0f); o7 = fmaxf(o7, 0.0f);
        }
        float* op = OUT + (size_t)node * HID;
        ((float4*)op)[2 * hl]     = make_float4(o0, o1, o2, o3);
        ((float4*)op)[2 * hl + 1] = make_float4(o4, o5, o6, o7);
    } else {
        int g = load_idx(batch, node);
        float* pp = &POOL[g * HID + hl * 8];
        asm volatile("red.global.add.v4.f32 [%0], {%1, %2, %3, %4};"
                     :: "l"(pp), "f"(o0), "f"(o1), "f"(o2), "f"(o3) : "memory");
        asm volatile("red.global.add.v4.f32 [%0], {%1, %2, %3, %4};"
                     :: "l"(pp + 4), "f"(o4), "f"(o5), "f"(o6), "f"(o7) : "memory");
        if (hl == 0) atomicAdd(&CNT[g], 1.0f);
    }
}

// ---------------- head: fc1 + batchnorm partial stats ----------------
__global__ void fc1_kernel(const float* __restrict__ POOL, const float* __restrict__ CNT,
                           const float* __restrict__ W, const float* __restrict__ b,
                           float* __restrict__ Y, float* __restrict__ BNSTAT) {
    int gi = blockIdx.x;
    int c  = threadIdx.x;
    __shared__ float gs[HID];
    float cnt = fmaxf(CNT[gi], 1.0f);
    gs[c] = POOL[gi * HID + c] / cnt;
    __syncthreads();
    float acc = b[c];
#pragma unroll 8
    for (int k = 0; k < HID; k++) acc = fmaf(gs[k], W[k * HID + c], acc);
    Y[gi * HID + c] = acc;
    atomicAdd(&BNSTAT[c], acc);
    atomicAdd(&BNSTAT[HID + c], acc * acc);
}

// ---------------- head: bn (inline stats) -> relu -> fc2 -> log_softmax -----
__global__ void head_kernel(const float* __restrict__ Y,
                            const float* __restrict__ BNSTAT,
                            const float* __restrict__ gamma, const float* __restrict__ beta,
                            const float* __restrict__ W2, const float* __restrict__ b2,
                            float* __restrict__ OUT) {
    int gi = blockIdx.x;
    int t  = threadIdx.x;
    __shared__ float ys[HID];
    __shared__ float os[OUT_CH];
    float s  = BNSTAT[t];
    float s2 = BNSTAT[HID + t];
    float mu  = s * (1.0f / N_GRAPHS);
    float var = s2 * (1.0f / N_GRAPHS) - mu * mu;
    float rsig = rsqrtf(var + 1e-5f);
    float v = Y[gi * HID + t];
    v = gamma[t] * (v - mu) * rsig + beta[t];
    ys[t] = fmaxf(v, 0.0f);
    __syncthreads();
    if (t < OUT_CH) {
        float acc = b2[t];
#pragma unroll 8
        for (int k = 0; k < HID; k++) acc = fmaf(ys[k], W2[k * OUT_CH + t], acc);
        os[t] = acc;
    }
    __syncthreads();
    if (t == 0) {
        float m = -1e30f;
#pragma unroll
        for (int j = 0; j < OUT_CH; j++) m = fmaxf(m, os[j]);
        float ssum = 0.0f;
#pragma unroll
        for (int j = 0; j < OUT_CH; j++) ssum += expf(os[j] - m);
        float lse = m + logf(ssum);
        for (int j = 0; j < OUT_CH; j++) OUT[gi * OUT_CH + j] = os[j] - lse;
    }
}

// ---------------- launch ----------------
extern "C" void kernel_launch(void* const* d_in, const int* in_sizes, int n_in,
                              void* d_out, int out_size) {
    const float* x      = (const float*)d_in[0];
    const void*  ei     = d_in[1];
    const void*  batch  = d_in[2];
    const float* W_l1   = (const float*)d_in[3];
    const float* b_l1   = (const float*)d_in[4];
    const float* W_r1   = (const float*)d_in[5];
    const float* b_r1   = (const float*)d_in[6];
    const float* att1   = (const float*)d_in[7];
    const float* bias1  = (const float*)d_in[8];
    const float* W_l2   = (const float*)d_in[9];
    const float* b_l2   = (const float*)d_in[10];
    const float* W_r2   = (const float*)d_in[11];
    const float* b_r2   = (const float*)d_in[12];
    const float* att2   = (const float*)d_in[13];
    const float* bias2  = (const float*)d_in[14];
    const float* W_fc1  = (const float*)d_in[15];
    const float* b_fc1  = (const float*)d_in[16];
    const float* gamma  = (const float*)d_in[17];
    const float* beta   = (const float*)d_in[18];
    const float* W_fc2  = (const float*)d_in[19];
    const float* b_fc2  = (const float*)d_in[20];
    float*       out    = (float*)d_out;

    __half2 *xl, *xr;
    float *h, *pool, *cnt, *y, *bnstat;
    int *deg, *rowptr, *cursor, *col, *bsum;
    cudaGetSymbolAddress((void**)&xl,     g_xl);
    cudaGetSymbolAddress((void**)&xr,     g_xr);
    cudaGetSymbolAddress((void**)&h,      g_h);
    cudaGetSymbolAddress((void**)&pool,   g_pool);
    cudaGetSymbolAddress((void**)&cnt,    g_cnt);
    cudaGetSymbolAddress((void**)&y,      g_y);
    cudaGetSymbolAddress((void**)&bnstat, g_bnstat);
    cudaGetSymbolAddress((void**)&deg,    g_deg);
    cudaGetSymbolAddress((void**)&rowptr, g_rowptr);
    cudaGetSymbolAddress((void**)&cursor, g_cursor);
    cudaGetSymbolAddress((void**)&col,    g_col);
    cudaGetSymbolAddress((void**)&bsum,   g_bsum);

    dim3 b256(256);
    bool par = (g_aux.s2 != nullptr) && (g_aux.evFork != nullptr) && (g_aux.evB != nullptr);

    detect_kernel<<<1, 1>>>((const int*)ei);

    if (par) {
        cudaEventRecord(g_aux.evFork, 0);
        cudaStreamWaitEvent(g_aux.s2, g_aux.evFork, 0);
        dual_linear_kernel<IN_CH><<<(N_NODES + 63) / 64, b256, 0, g_aux.s2>>>(
            x, W_l1, b_l1, W_r1, b_r1, xl, xr);
        cudaMemsetAsync(pool, 0, N_GRAPHS * HID * sizeof(float), g_aux.s2);
        cudaMemsetAsync(cnt, 0, N_GRAPHS * sizeof(float), g_aux.s2);
        cudaMemsetAsync(bnstat, 0, 2 * HID * sizeof(float), g_aux.s2);
        cudaEventRecord(g_aux.evB, g_aux.s2);
    }

    // ---- CSR build on stream 0 ----
    cudaMemsetAsync(deg, 0, N_NODES * sizeof(int), 0);
    hist_kernel<<<(E_TOT / 2 + 255) / 256, b256>>>(ei, deg);
    scan1_kernel<<<N_SCAN_BLKS, SCAN_BLK>>>(deg, rowptr, bsum);
    scan2_kernel<<<1, 32>>>(bsum);
    scan3_kernel<<<N_SCAN_BLKS, SCAN_BLK>>>(rowptr, bsum, cursor);
    scatter_kernel<<<(E_TOT / 2 + 255) / 256, b256>>>(ei, cursor, col);

    if (par) {
        cudaStreamWaitEvent(0, g_aux.evB, 0);
    } else {
        dual_linear_kernel<IN_CH><<<(N_NODES + 63) / 64, b256>>>(x, W_l1, b_l1, W_r1, b_r1, xl, xr);
        cudaMemsetAsync(pool, 0, N_GRAPHS * HID * sizeof(float), 0);
        cudaMemsetAsync(cnt, 0, N_GRAPHS * sizeof(float), 0);
        cudaMemsetAsync(bnstat, 0, 2 * HID * sizeof(float), 0);
    }

    // ---- layer 1 aggregation ----
    gat_agg_kernel<0><<<N_NODES / 32, b256>>>(rowptr, col, xl, xr, att1, bias1,
                                              h, 1, batch, pool, cnt);

    // ---- layer 2 (pool fused into aggregation) ----
    dual_linear_kernel<HID><<<(N_NODES + 63) / 64, b256>>>(h, W_l2, b_l2, W_r2, b_r2, xl, xr);
    gat_agg_kernel<1><<<N_NODES / 32, b256>>>(rowptr, col, xl, xr, att2, bias2,
                                              h, 0, batch, pool, cnt);

    // ---- head ----
    fc1_kernel<<<N_GRAPHS, HID>>>(pool, cnt, W_fc1, b_fc1, y, bnstat);
    head_kernel<<<N_GRAPHS, HID>>>(y, bnstat, gamma, beta, W_fc2, b_fc2, out);
}

// round 16
// speedup vs baseline: 1.3576x; 1.3576x over previous
#include <cuda_runtime.h>
#include <cuda_fp16.h>
#include <math.h>

#define N_NODES   100000
#define N_EDGES   1600000
#define E_TOT     (N_EDGES + N_NODES)
#define IN_CH     128
#define HID       64
#define OUT_CH    16
#define N_GRAPHS  512
#define NEG_SLOPE 0.2f

#define SCAN_BLK  512
#define N_SCAN_BLKS ((N_NODES + SCAN_BLK - 1) / SCAN_BLK)   // 196

// ---------------- scratch (device globals; no allocation allowed) ----------------
__device__ __half2 g_xl[(size_t)N_NODES * 32];
__device__ __half2 g_xr[(size_t)N_NODES * 32];
__device__ float   g_h[(size_t)N_NODES * HID];
__device__ float   g_pool[N_GRAPHS * HID];
__device__ float   g_cnt[N_GRAPHS];
__device__ float   g_y[N_GRAPHS * HID];
__device__ float   g_bnstat[2 * HID];   // [0:64) sum, [64:128) sum of squares
__device__ int     g_is64;

// CSR scratch
__device__ int g_deg[N_NODES];
__device__ int g_rowptr[N_NODES + 1];
__device__ int g_cursor[N_NODES];
__device__ int g_col[E_TOT];
__device__ int g_bsum[N_SCAN_BLKS];

// ---------------- aux streams/events ----------------
namespace {
struct Aux {
    cudaStream_t s2 = nullptr;
    cudaEvent_t  evFork = nullptr, evB = nullptr;
    Aux() {
        if (cudaStreamCreateWithFlags(&s2, cudaStreamNonBlocking) != cudaSuccess) {
            s2 = nullptr; return;
        }
        if (cudaEventCreateWithFlags(&evFork, cudaEventDisableTiming) != cudaSuccess) {
            evFork = nullptr; return;
        }
        if (cudaEventCreateWithFlags(&evB, cudaEventDisableTiming) != cudaSuccess) {
            evB = nullptr; return;
        }
    }
};
Aux g_aux;
}

// ---------------- packed helpers ----------------
__device__ __forceinline__ unsigned long long pack2(float lo, float hi) {
    unsigned long long r;
    asm("mov.b64 %0, {%1, %2};" : "=l"(r) : "f"(lo), "f"(hi));
    return r;
}
__device__ __forceinline__ void unpack2(unsigned long long v, float& lo, float& hi) {
    asm("mov.b64 {%0, %1}, %2;" : "=f"(lo), "=f"(hi) : "l"(v));
}
__device__ __forceinline__ void fma2(unsigned long long& d,
                                     unsigned long long a, unsigned long long b) {
    asm("fma.rn.f32x2 %0, %1, %2, %0;" : "+l"(d) : "l"(a), "l"(b));
}
__device__ __forceinline__ unsigned h2u(__half2 h) { return *(unsigned*)&h; }
__device__ __forceinline__ __half2 u2h(unsigned u) { return *(__half2*)&u; }

// ---------------- dtype detection ----------------
__global__ void detect_kernel(const int* __restrict__ w) {
    int ok64 = 1;
    for (int i = 0; i < 32; i++)
        if (w[2 * i + 1] != 0) ok64 = 0;
    g_is64 = ok64;
}

__device__ __forceinline__ int load_idx(const void* p, long long i) {
    if (g_is64) return (int)((const long long*)p)[i];
    return ((const int*)p)[i];
}

// ---------------- CSR build ----------------
__global__ void hist_kernel(const void* __restrict__ ei, int* __restrict__ deg) {
    int t = blockIdx.x * blockDim.x + threadIdx.x;
#pragma unroll
    for (int u = 0; u < 2; u++) {
        int e = t * 2 + u;
        if (e >= E_TOT) return;
        int dst = (e < N_EDGES) ? load_idx(ei, (long long)N_EDGES + e) : e - N_EDGES;
        atomicAdd(&deg[dst], 1);
    }
}

__global__ void scan1_kernel(const int* __restrict__ deg, int* __restrict__ rowptr,
                             int* __restrict__ bsum) {
    __shared__ int sh[SCAN_BLK];
    int i = blockIdx.x * SCAN_BLK + threadIdx.x;
    int v = (i < N_NODES) ? deg[i] : 0;
    sh[threadIdx.x] = v;
    __syncthreads();
    for (int o = 1; o < SCAN_BLK; o <<= 1) {
        int t = (threadIdx.x >= o) ? sh[threadIdx.x - o] : 0;
        __syncthreads();
        sh[threadIdx.x] += t;
        __syncthreads();
    }
    if (i < N_NODES) rowptr[i] = sh[threadIdx.x] - v;
    if (threadIdx.x == SCAN_BLK - 1) bsum[blockIdx.x] = sh[SCAN_BLK - 1];
}

__global__ void scan2_kernel(int* __restrict__ bsum) {
    int lane = threadIdx.x & 31;
    int acc = 0;
    for (int base = 0; base < N_SCAN_BLKS; base += 32) {
        int i = base + lane;
        int orig = (i < N_SCAN_BLKS) ? bsum[i] : 0;
        int v = orig;
#pragma unroll
        for (int o = 1; o < 32; o <<= 1) {
            int t = __shfl_up_sync(0xffffffffu, v, o);
            if (lane >= o) v += t;
        }
        if (i < N_SCAN_BLKS) bsum[i] = acc + v - orig;
        acc += __shfl_sync(0xffffffffu, v, 31);
    }
}

__global__ void scan3_kernel(int* __restrict__ rowptr, const int* __restrict__ bsum,
                             int* __restrict__ cursor) {
    int i = blockIdx.x * SCAN_BLK + threadIdx.x;
    if (i < N_NODES) {
        int v = rowptr[i] + bsum[blockIdx.x];
        rowptr[i] = v;
        cursor[i] = v;
    }
    if (i == 0) rowptr[N_NODES] = E_TOT;
}

__global__ void scatter_kernel(const void* __restrict__ ei,
                               int* __restrict__ cursor, int* __restrict__ col) {
    int t = blockIdx.x * blockDim.x + threadIdx.x;
#pragma unroll
    for (int u = 0; u < 2; u++) {
        int e = t * 2 + u;
        if (e >= E_TOT) return;
        int src, dst;
        if (e < N_EDGES) {
            src = load_idx(ei, e);
            dst = load_idx(ei, (long long)N_EDGES + e);
        } else {
            src = dst = e - N_EDGES;
        }
        int pos = atomicAdd(&cursor[dst], 1);
        col[pos] = src;
    }
}

// ---------------- dual linear: 64 nodes/block, 8 nodes x 2 ch/thread ---------
template <int IN>
__global__ __launch_bounds__(256) void dual_linear_kernel(
        const float* __restrict__ X,
        const float* __restrict__ Wl, const float* __restrict__ bl,
        const float* __restrict__ Wr, const float* __restrict__ br,
        __half2* __restrict__ XL, __half2* __restrict__ XR) {
    int node0 = blockIdx.x * 64;
    int c2    = threadIdx.x & 31;
    int sub   = threadIdx.x >> 5;
    __shared__ float xs[64][IN];

    for (int i = threadIdx.x; i < 64 * (IN / 4); i += 256) {
        int row = i / (IN / 4), colx = i % (IN / 4);
        int gr = node0 + row;
        if (gr >= N_NODES) gr = N_NODES - 1;
        ((float4*)xs[row])[colx] = ((const float4*)(X + (size_t)gr * IN))[colx];
    }
    __syncthreads();

    unsigned long long accl[8], accr[8];
    unsigned long long blv = *(const unsigned long long*)&bl[2 * c2];
    unsigned long long brv = *(const unsigned long long*)&br[2 * c2];
#pragma unroll
    for (int n = 0; n < 8; n++) { accl[n] = blv; accr[n] = brv; }

    const float (*xp)[IN] = (const float (*)[IN])xs[sub * 8];

    for (int k0 = 0; k0 < IN; k0 += 4) {
        float4 xv[8];
#pragma unroll
        for (int n = 0; n < 8; n++)
            xv[n] = *(const float4*)&xp[n][k0];
#pragma unroll
        for (int kk = 0; kk < 4; kk++) {
            unsigned long long wl2 =
                *(const unsigned long long*)&Wl[(k0 + kk) * HID + 2 * c2];
            unsigned long long wr2 =
                *(const unsigned long long*)&Wr[(k0 + kk) * HID + 2 * c2];
#pragma unroll
            for (int n = 0; n < 8; n++) {
                float xvv = (kk == 0) ? xv[n].x : (kk == 1) ? xv[n].y
                          : (kk == 2) ? xv[n].z : xv[n].w;
                unsigned long long xb = pack2(xvv, xvv);
                fma2(accl[n], xb, wl2);
                fma2(accr[n], xb, wr2);
            }
        }
    }

#pragma unroll
    for (int n = 0; n < 8; n++) {
        int node = node0 + sub * 8 + n;
        if (node < N_NODES) {
            float l0, l1, r0, r1;
            unpack2(accl[n], l0, l1);
            unpack2(accr[n], r0, r1);
            XL[(size_t)node * 32 + c2] = __floats2half2_rn(l0, l1);
            XR[(size_t)node * 32 + c2] = __floats2half2_rn(r0, r1);
        }
    }
}

// ---------------- GAT aggregate: 4 nodes/warp, 8 lanes/node, half2 e-path,
// fp32 accumulators (R14 exact) ----------------------------------------------
template <int POOL_MODE>
__global__ __launch_bounds__(256) void gat_agg_kernel(
        const int* __restrict__ rowptr, const int* __restrict__ col,
        const __half2* __restrict__ XL, const __half2* __restrict__ XR,
        const float* __restrict__ att, const float* __restrict__ bias,
        float* __restrict__ OUT, int do_relu,
        const void* __restrict__ batch, float* __restrict__ POOL,
        float* __restrict__ CNT) {
    int warp = threadIdx.x >> 5;
    int lane = threadIdx.x & 31;
    int q    = lane >> 3;      // 0..3: node slot within warp
    int hl   = lane & 7;       // channels 8*hl .. 8*hl+7
    int node = blockIdx.x * 32 + warp * 4 + q;   // grid sized exactly

    uint4 rraw = ((const uint4*)(XR + (size_t)node * 32))[hl];
    __half2 r0 = u2h(rraw.x), r1 = u2h(rraw.y), r2 = u2h(rraw.z), r3 = u2h(rraw.w);

    float4 aLo = ((const float4*)att)[2 * hl];
    float4 aHi = ((const float4*)att)[2 * hl + 1];
    __half2 at0 = __floats2half2_rn(aLo.x, aLo.y);
    __half2 at1 = __floats2half2_rn(aLo.z, aLo.w);
    __half2 at2 = __floats2half2_rn(aHi.x, aHi.y);
    __half2 at3 = __floats2half2_rn(aHi.z, aHi.w);
    const __half2 slope2 = __float2half2_rn(NEG_SLOPE);

    int beg = rowptr[node], end = rowptr[node + 1];
    int deg = end - beg;
    int m = deg;
    m = max(m, __shfl_xor_sync(0xffffffffu, m, 8));
    m = max(m, __shfl_xor_sync(0xffffffffu, m, 16));
    int maxit = m;

    float acc0 = 0.0f, acc1 = 0.0f, acc2 = 0.0f, acc3 = 0.0f;
    float acc4 = 0.0f, acc5 = 0.0f, acc6 = 0.0f, acc7 = 0.0f, z = 0.0f;

    int e = beg;
    for (int it = 0; it < maxit; it += 2, e += 2) {
        bool v[2] = { e < end, e + 1 < end };
        int s[2];
        s[0] = v[0] ? __ldg(&col[e])     : node;
        s[1] = v[1] ? __ldg(&col[e + 1]) : node;

        uint4 lraw[2];
        lraw[0] = ((const uint4*)(XL + (size_t)s[0] * 32))[hl];
        lraw[1] = ((const uint4*)(XL + (size_t)s[1] * 32))[hl];

        __half2 p2[2];
#pragma unroll
        for (int u = 0; u < 2; u++) {
            __half2 h0 = __hadd2(u2h(lraw[u].x), r0);
            __half2 h1 = __hadd2(u2h(lraw[u].y), r1);
            __half2 h2 = __hadd2(u2h(lraw[u].z), r2);
            __half2 h3 = __hadd2(u2h(lraw[u].w), r3);
            h0 = __hmax2(h0, __hmul2(h0, slope2));
            h1 = __hmax2(h1, __hmul2(h1, slope2));
            h2 = __hmax2(h2, __hmul2(h2, slope2));
            h3 = __hmax2(h3, __hmul2(h3, slope2));
            __half2 t = __hfma2(h0, at0, __hmul2(h1, at1));
            t = __hfma2(h2, at2, t);
            p2[u] = __hfma2(h3, at3, t);
        }
#pragma unroll
        for (int o = 4; o; o >>= 1) {
#pragma unroll
            for (int u = 0; u < 2; u++)
                p2[u] = __hadd2(p2[u], u2h(__shfl_xor_sync(0xffffffffu, h2u(p2[u]), o)));
        }
#pragma unroll
        for (int u = 0; u < 2; u++) {
            float2 pf = __half22float2(p2[u]);
            float w = v[u] ? __expf(pf.x + pf.y) : 0.0f;
            z += w;
            float2 f0 = __half22float2(u2h(lraw[u].x));
            float2 f1 = __half22float2(u2h(lraw[u].y));
            float2 f2 = __half22float2(u2h(lraw[u].z));
            float2 f3 = __half22float2(u2h(lraw[u].w));
            acc0 = fmaf(w, f0.x, acc0); acc1 = fmaf(w, f0.y, acc1);
            acc2 = fmaf(w, f1.x, acc2); acc3 = fmaf(w, f1.y, acc3);
            acc4 = fmaf(w, f2.x, acc4); acc5 = fmaf(w, f2.y, acc5);
            acc6 = fmaf(w, f3.x, acc6); acc7 = fmaf(w, f3.y, acc7);
        }
    }

    float inv = 1.0f / z;   // self-loop guarantees z > 0
    float4 bv0 = ((const float4*)bias)[2 * hl];
    float4 bv1 = ((const float4*)bias)[2 * hl + 1];
    float o0 = acc0 * inv + bv0.x;
    float o1 = acc1 * inv + bv0.y;
    float o2 = acc2 * inv + bv0.z;
    float o3 = acc3 * inv + bv0.w;
    float o4 = acc4 * inv + bv1.x;
    float o5 = acc5 * inv + bv1.y;
    float o6 = acc6 * inv + bv1.z;
    float o7 = acc7 * inv + bv1.w;

    if (POOL_MODE == 0) {
        if (do_relu) {
            o0 = fmaxf(o0, 0.0f); o1 = fmaxf(o1, 0.0f);
            o2 = fmaxf(o2, 0.0f); o3 = fmaxf(o3, 0.0f);
            o4 = fmaxf(o4, 0.0f); o5 = fmaxf(o5, 0.0f);
            o6 = fmaxf(o6, 0.0f); o7 = fmaxf(o7, 0.0f);
        }
        float* op = OUT + (size_t)node * HID;
        ((float4*)op)[2 * hl]     = make_float4(o0, o1, o2, o3);
        ((float4*)op)[2 * hl + 1] = make_float4(o4, o5, o6, o7);
    } else {
        int g = load_idx(batch, node);
        float* pp = &POOL[g * HID + hl * 8];
        asm volatile("red.global.add.v4.f32 [%0], {%1, %2, %3, %4};"
                     :: "l"(pp), "f"(o0), "f"(o1), "f"(o2), "f"(o3) : "memory");
        asm volatile("red.global.add.v4.f32 [%0], {%1, %2, %3, %4};"
                     :: "l"(pp + 4), "f"(o4), "f"(o5), "f"(o6), "f"(o7) : "memory");
        if (hl == 0) atomicAdd(&CNT[g], 1.0f);
    }
}

// ---------------- head: fc1 + batchnorm partial stats ----------------
__global__ void fc1_kernel(const float* __restrict__ POOL, const float* __restrict__ CNT,
                           const float* __restrict__ W, const float* __restrict__ b,
                           float* __restrict__ Y, float* __restrict__ BNSTAT) {
    int gi = blockIdx.x;
    int c  = threadIdx.x;
    __shared__ float gs[HID];
    float cnt = fmaxf(CNT[gi], 1.0f);
    gs[c] = POOL[gi * HID + c] / cnt;
    __syncthreads();
    float acc = b[c];
#pragma unroll 8
    for (int k = 0; k < HID; k++) acc = fmaf(gs[k], W[k * HID + c], acc);
    Y[gi * HID + c] = acc;
    atomicAdd(&BNSTAT[c], acc);
    atomicAdd(&BNSTAT[HID + c], acc * acc);
}

// ---------------- head: bn (inline stats) -> relu -> fc2 -> log_softmax -----
__global__ void head_kernel(const float* __restrict__ Y,
                            const float* __restrict__ BNSTAT,
                            const float* __restrict__ gamma, const float* __restrict__ beta,
                            const float* __restrict__ W2, const float* __restrict__ b2,
                            float* __restrict__ OUT) {
    int gi = blockIdx.x;
    int t  = threadIdx.x;
    __shared__ float ys[HID];
    __shared__ float os[OUT_CH];
    float s  = BNSTAT[t];
    float s2 = BNSTAT[HID + t];
    float mu  = s * (1.0f / N_GRAPHS);
    float var = s2 * (1.0f / N_GRAPHS) - mu * mu;
    float rsig = rsqrtf(var + 1e-5f);
    float v = Y[gi * HID + t];
    v = gamma[t] * (v - mu) * rsig + beta[t];
    ys[t] = fmaxf(v, 0.0f);
    __syncthreads();
    if (t < OUT_CH) {
        float acc = b2[t];
#pragma unroll 8
        for (int k = 0; k < HID; k++) acc = fmaf(ys[k], W2[k * OUT_CH + t], acc);
        os[t] = acc;
    }
    __syncthreads();
    if (t == 0) {
        float m = -1e30f;
#pragma unroll
        for (int j = 0; j < OUT_CH; j++) m = fmaxf(m, os[j]);
        float ssum = 0.0f;
#pragma unroll
        for (int j = 0; j < OUT_CH; j++) ssum += expf(os[j] - m);
        float lse = m + logf(ssum);
        for (int j = 0; j < OUT_CH; j++) OUT[gi * OUT_CH + j] = os[j] - lse;
    }
}

// ---------------- launch ----------------
extern "C" void kernel_launch(void* const* d_in, const int* in_sizes, int n_in,
                              void* d_out, int out_size) {
    const float* x      = (const float*)d_in[0];
    const void*  ei     = d_in[1];
    const void*  batch  = d_in[2];
    const float* W_l1   = (const float*)d_in[3];
    const float* b_l1   = (const float*)d_in[4];
    const float* W_r1   = (const float*)d_in[5];
    const float* b_r1   = (const float*)d_in[6];
    const float* att1   = (const float*)d_in[7];
    const float* bias1  = (const float*)d_in[8];
    const float* W_l2   = (const float*)d_in[9];
    const float* b_l2   = (const float*)d_in[10];
    const float* W_r2   = (const float*)d_in[11];
    const float* b_r2   = (const float*)d_in[12];
    const float* att2   = (const float*)d_in[13];
    const float* bias2  = (const float*)d_in[14];
    const float* W_fc1  = (const float*)d_in[15];
    const float* b_fc1  = (const float*)d_in[16];
    const float* gamma  = (const float*)d_in[17];
    const float* beta   = (const float*)d_in[18];
    const float* W_fc2  = (const float*)d_in[19];
    const float* b_fc2  = (const float*)d_in[20];
    float*       out    = (float*)d_out;

    __half2 *xl, *xr;
    float *h, *pool, *cnt, *y, *bnstat;
    int *deg, *rowptr, *cursor, *col, *bsum;
    cudaGetSymbolAddress((void**)&xl,     g_xl);
    cudaGetSymbolAddress((void**)&xr,     g_xr);
    cudaGetSymbolAddress((void**)&h,      g_h);
    cudaGetSymbolAddress((void**)&pool,   g_pool);
    cudaGetSymbolAddress((void**)&cnt,    g_cnt);
    cudaGetSymbolAddress((void**)&y,      g_y);
    cudaGetSymbolAddress((void**)&bnstat, g_bnstat);
    cudaGetSymbolAddress((void**)&deg,    g_deg);
    cudaGetSymbolAddress((void**)&rowptr, g_rowptr);
    cudaGetSymbolAddress((void**)&cursor, g_cursor);
    cudaGetSymbolAddress((void**)&col,    g_col);
    cudaGetSymbolAddress((void**)&bsum,   g_bsum);

    dim3 b256(256);
    bool par = (g_aux.s2 != nullptr) && (g_aux.evFork != nullptr) && (g_aux.evB != nullptr);

    detect_kernel<<<1, 1>>>((const int*)ei);

    if (par) {
        cudaEventRecord(g_aux.evFork, 0);
        cudaStreamWaitEvent(g_aux.s2, g_aux.evFork, 0);
        dual_linear_kernel<IN_CH><<<(N_NODES + 63) / 64, b256, 0, g_aux.s2>>>(
            x, W_l1, b_l1, W_r1, b_r1, xl, xr);
        cudaMemsetAsync(pool, 0, N_GRAPHS * HID * sizeof(float), g_aux.s2);
        cudaMemsetAsync(cnt, 0, N_GRAPHS * sizeof(float), g_aux.s2);
        cudaMemsetAsync(bnstat, 0, 2 * HID * sizeof(float), g_aux.s2);
        cudaEventRecord(g_aux.evB, g_aux.s2);
    }

    // ---- CSR build on stream 0 ----
    cudaMemsetAsync(deg, 0, N_NODES * sizeof(int), 0);
    hist_kernel<<<(E_TOT / 2 + 255) / 256, b256>>>(ei, deg);
    scan1_kernel<<<N_SCAN_BLKS, SCAN_BLK>>>(deg, rowptr, bsum);
    scan2_kernel<<<1, 32>>>(bsum);
    scan3_kernel<<<N_SCAN_BLKS, SCAN_BLK>>>(rowptr, bsum, cursor);
    scatter_kernel<<<(E_TOT / 2 + 255) / 256, b256>>>(ei, cursor, col);

    if (par) {
        cudaStreamWaitEvent(0, g_aux.evB, 0);
    } else {
        dual_linear_kernel<IN_CH><<<(N_NODES + 63) / 64, b256>>>(x, W_l1, b_l1, W_r1, b_r1, xl, xr);
        cudaMemsetAsync(pool, 0, N_GRAPHS * HID * sizeof(float), 0);
        cudaMemsetAsync(cnt, 0, N_GRAPHS * sizeof(float), 0);
        cudaMemsetAsync(bnstat, 0, 2 * HID * sizeof(float), 0);
    }

    // ---- layer 1 aggregation ----
    gat_agg_kernel<0><<<N_NODES / 32, b256>>>(rowptr, col, xl, xr, att1, bias1,
                                              h, 1, batch, pool, cnt);

    // ---- layer 2 (pool fused into aggregation) ----
    dual_linear_kernel<HID><<<(N_NODES + 63) / 64, b256>>>(h, W_l2, b_l2, W_r2, b_r2, xl, xr);
    gat_agg_kernel<1><<<N_NODES / 32, b256>>>(rowptr, col, xl, xr, att2, bias2,
                                              h, 0, batch, pool, cnt);

    // ---- head ----
    fc1_kernel<<<N_GRAPHS, HID>>>(pool, cnt, W_fc1, b_fc1, y, bnstat);
    head_kernel<<<N_GRAPHS, HID>>>(y, bnstat, gamma, beta, W_fc2, b_fc2, out);
}